// round 1
// baseline (speedup 1.0000x reference)
#include <cuda_runtime.h>
#include <cuda_bf16.h>
#include <math.h>

// Problem constants
#define B_SZ    1024
#define HID     512
#define INSZ    64
#define TSTEPS  256
#define GATES   2048           // 4*HID
#define KTOT    576            // INSZ + HID

// GEMM tile config
#define BM 128                 // batch rows per block
#define BN 128                 // packed gate cols per block (= 32 hidden n)
#define BK 32

// -------- device scratch (no allocations allowed) --------
__device__ float g_Wpack[GATES * KTOT];   // [n*4+g][k] packed weights
__device__ float g_bias[GATES];           // b_ih + b_hh in packed col order
__device__ float g_h[2][B_SZ * HID];
__device__ float g_c[2][B_SZ * HID];

// ---------------------------------------------------------
// Prepack: Wpack[col = n*4+g][k] = k<64 ? W_ih[g*512+n][k] : W_hh[g*512+n][k-64]
// ---------------------------------------------------------
__global__ void prepack_kernel(const float* __restrict__ W_ih,
                               const float* __restrict__ W_hh,
                               const float* __restrict__ b_ih,
                               const float* __restrict__ b_hh)
{
    int idx = blockIdx.x * blockDim.x + threadIdx.x;
    int stride = gridDim.x * blockDim.x;
    const int total = GATES * KTOT;
    for (int i = idx; i < total; i += stride) {
        int col = i / KTOT;
        int k   = i - col * KTOT;
        int n = col >> 2;
        int g = col & 3;
        int row = g * HID + n;
        float v = (k < INSZ) ? W_ih[row * INSZ + k]
                             : W_hh[row * HID + (k - INSZ)];
        g_Wpack[i] = v;
    }
    for (int i = idx; i < GATES; i += stride) {
        int n = i >> 2;
        int g = i & 3;
        int row = g * HID + n;
        g_bias[i] = b_ih[row] + b_hh[row];
    }
}

// ---------------------------------------------------------
// Init: copy h0, c0 into buffer 0
// ---------------------------------------------------------
__global__ void init_state_kernel(const float* __restrict__ h0,
                                  const float* __restrict__ c0)
{
    int idx = blockIdx.x * blockDim.x + threadIdx.x;
    int stride = gridDim.x * blockDim.x;
    for (int i = idx; i < B_SZ * HID; i += stride) {
        g_h[0][i] = h0[i];
        g_c[0][i] = c0[i];
    }
}

// ---------------------------------------------------------
// One LSTM step: gates = [x_t | h_prev] @ Wpack^T + bias ; then LSTM update.
// Each block: BM=128 batch rows x BN=128 packed gate cols (32 hidden units).
// ---------------------------------------------------------
__global__ __launch_bounds__(256, 1)
void lstm_step_kernel(const float* __restrict__ x, int t, int buf)
{
    __shared__ float sA[BK][BM];
    __shared__ float sB[BK][BN];

    const int tid = threadIdx.x;           // 0..255
    const int tx  = tid & 15;              // col group (16)
    const int ty  = tid >> 4;              // row group (16)
    const int row0 = blockIdx.y * BM;      // batch base
    const int col0 = blockIdx.x * BN;      // packed gate col base

    const float* __restrict__ hprev = g_h[buf];
    const float* __restrict__ cprev = g_c[buf];
    float* __restrict__ hnext = g_h[buf ^ 1];
    float* __restrict__ cnext = g_c[buf ^ 1];

    const int ldr = tid >> 1;              // 0..127: A row / B col within tile
    const int ldk = (tid & 1) * 16;        // k sub-offset 0 or 16

    float acc[8][8];
#pragma unroll
    for (int i = 0; i < 8; ++i)
#pragma unroll
        for (int j = 0; j < 8; ++j) acc[i][j] = 0.f;

    for (int kb = 0; kb < KTOT; kb += BK) {
        // ---- load A tile (128 rows x 32 k), source = x_t (kb<64) or h_prev ----
#pragma unroll
        for (int it = 0; it < 4; ++it) {
            int k = ldk + it * 4;
            float4 v;
            if (kb < INSZ) {
                v = *(const float4*)(x + (size_t)(row0 + ldr) * (TSTEPS * INSZ)
                                       + t * INSZ + kb + k);
            } else {
                v = *(const float4*)(hprev + (size_t)(row0 + ldr) * HID
                                           + (kb - INSZ) + k);
            }
            sA[k + 0][ldr] = v.x; sA[k + 1][ldr] = v.y;
            sA[k + 2][ldr] = v.z; sA[k + 3][ldr] = v.w;
        }
        // ---- load B tile (128 cols x 32 k) from packed weights ----
#pragma unroll
        for (int it = 0; it < 4; ++it) {
            int k = ldk + it * 4;
            float4 v = *(const float4*)(g_Wpack + (size_t)(col0 + ldr) * KTOT
                                                + kb + k);
            sB[k + 0][ldr] = v.x; sB[k + 1][ldr] = v.y;
            sB[k + 2][ldr] = v.z; sB[k + 3][ldr] = v.w;
        }
        __syncthreads();

#pragma unroll
        for (int k = 0; k < BK; ++k) {
            float4 a0 = *(const float4*)&sA[k][ty * 8];
            float4 a1 = *(const float4*)&sA[k][ty * 8 + 4];
            float4 b0 = *(const float4*)&sB[k][tx * 8];
            float4 b1 = *(const float4*)&sB[k][tx * 8 + 4];
            float ra[8] = {a0.x, a0.y, a0.z, a0.w, a1.x, a1.y, a1.z, a1.w};
            float rb[8] = {b0.x, b0.y, b0.z, b0.w, b1.x, b1.y, b1.z, b1.w};
#pragma unroll
            for (int i = 0; i < 8; ++i)
#pragma unroll
                for (int j = 0; j < 8; ++j)
                    acc[i][j] += ra[i] * rb[j];
        }
        __syncthreads();
    }

    // ---- epilogue: bias + activations + c/h update ----
    // thread's cols: tx*8 + j  -> two hidden units (4 gates each, i,f,g,o adjacent)
#pragma unroll
    for (int i = 0; i < 8; ++i) {
        int b = row0 + ty * 8 + i;
#pragma unroll
        for (int jj = 0; jj < 2; ++jj) {
            int pc = col0 + tx * 8 + jj * 4;   // packed col of gate i for unit n
            int n  = pc >> 2;
            float gi = acc[i][jj * 4 + 0] + g_bias[pc + 0];
            float gf = acc[i][jj * 4 + 1] + g_bias[pc + 1];
            float gg = acc[i][jj * 4 + 2] + g_bias[pc + 2];
            float go = acc[i][jj * 4 + 3] + g_bias[pc + 3];
            float ig = 1.f / (1.f + expf(-gi));
            float fg = 1.f / (1.f + expf(-gf));
            float gt = tanhf(gg);
            float og = 1.f / (1.f + expf(-go));
            float cn = fg * cprev[(size_t)b * HID + n] + ig * gt;
            float hn = og * tanhf(cn);
            cnext[(size_t)b * HID + n] = cn;
            hnext[(size_t)b * HID + n] = hn;
        }
    }
}

// ---------------------------------------------------------
// Final linear: out[b][w] = h_T[b,:] . W_lin[w,:] + b_lin[w]
// grid = B, block = (32, 10): one warp per output class
// ---------------------------------------------------------
__global__ void final_linear_kernel(const float* __restrict__ W_lin,
                                    const float* __restrict__ b_lin,
                                    float* __restrict__ out, int buf)
{
    int b = blockIdx.x;
    int w = threadIdx.y;      // 0..9
    int lane = threadIdx.x;   // 0..31
    const float* h = g_h[buf] + (size_t)b * HID;
    const float* wl = W_lin + (size_t)w * HID;
    float s = 0.f;
#pragma unroll
    for (int k = lane; k < HID; k += 32)
        s += h[k] * wl[k];
#pragma unroll
    for (int off = 16; off; off >>= 1)
        s += __shfl_down_sync(0xffffffffu, s, off);
    if (lane == 0)
        out[b * 10 + w] = s + b_lin[w];
}

// ---------------------------------------------------------
extern "C" void kernel_launch(void* const* d_in, const int* in_sizes, int n_in,
                              void* d_out, int out_size)
{
    const float* x     = (const float*)d_in[0];
    const float* h0    = (const float*)d_in[1];
    const float* c0    = (const float*)d_in[2];
    const float* W_ih  = (const float*)d_in[3];
    const float* W_hh  = (const float*)d_in[4];
    const float* b_ih  = (const float*)d_in[5];
    const float* b_hh  = (const float*)d_in[6];
    const float* W_lin = (const float*)d_in[7];
    const float* b_lin = (const float*)d_in[8];
    float* out = (float*)d_out;

    prepack_kernel<<<1024, 256>>>(W_ih, W_hh, b_ih, b_hh);
    init_state_kernel<<<512, 512>>>(h0, c0);

    dim3 grid(GATES / BN, B_SZ / BM);   // 16 x 8 = 128 blocks
    for (int t = 0; t < TSTEPS; ++t) {
        lstm_step_kernel<<<grid, 256>>>(x, t, t & 1);
    }

    final_linear_kernel<<<B_SZ, dim3(32, 10)>>>(W_lin, b_lin, out, TSTEPS & 1);
}

// round 3
// speedup vs baseline: 1.5339x; 1.5339x over previous
#include <cuda_runtime.h>
#include <cuda_bf16.h>
#include <math.h>
#include <stdint.h>

// ---------------- problem constants ----------------
#define B_SZ   1024
#define HID    512
#define INSZ   64
#define TSTEPS 256
#define GATES  2048              // 4*HID
#define KTOT   576               // INSZ + HID
#define XCOLS  (TSTEPS * INSZ)   // 16384

// ---------------- GEMM tiling ----------------
#define BM 128
#define BN 128
#define KTILE 64                 // 64 bf16 = 128 bytes per row
#define NKT 27                   // 3 segments (hi*hi, lo*hi, hi*lo) x 9 k-chunks

// SW128 swizzle (Swizzle<3,4,3>) on byte offsets within a tile
#define SWZ(o) ((o) ^ (((o) >> 3) & 0x70))

// dynamic smem layout
#define SOFF_BIAS  0                       // 128 floats
#define SOFF_A     1024                    // 2 x 16KB
#define SOFF_B     (1024 + 32768)          // 2 x 16KB
#define SMEM_TOTAL (1024 + 65536)

// ---------------- device scratch (no allocs allowed) ----------------
static __device__ __nv_bfloat16 g_xh[(size_t)B_SZ * XCOLS];
static __device__ __nv_bfloat16 g_xl[(size_t)B_SZ * XCOLS];
static __device__ __nv_bfloat16 g_Bh[GATES * KTOT];   // packed col = n*4+g
static __device__ __nv_bfloat16 g_Bl[GATES * KTOT];
static __device__ float        g_bias[GATES];
static __device__ __nv_bfloat16 g_hh[2][B_SZ * HID];
static __device__ __nv_bfloat16 g_hl[2][B_SZ * HID];
static __device__ float        g_c[B_SZ * HID];

// ---------------- PTX helpers ----------------
__device__ __forceinline__ uint32_t smem_u32(const void* p) {
    uint32_t a;
    asm("{ .reg .u64 t; cvta.to.shared.u64 t, %1; cvt.u32.u64 %0, t; }"
        : "=r"(a) : "l"(p));
    return a;
}

__device__ __forceinline__ void cp16(uint32_t dst, const void* src) {
    asm volatile("cp.async.cg.shared.global [%0], [%1], 16;"
                 :: "r"(dst), "l"(src));
}
__device__ __forceinline__ void cp_commit() {
    asm volatile("cp.async.commit_group;" ::: "memory");
}
template<int N>
__device__ __forceinline__ void cp_wait() {
    asm volatile("cp.async.wait_group %0;" :: "n"(N) : "memory");
}

__device__ __forceinline__ void ldsm4(uint32_t* r, uint32_t addr) {
    asm volatile("ldmatrix.sync.aligned.m8n8.x4.shared.b16 {%0,%1,%2,%3}, [%4];"
                 : "=r"(r[0]), "=r"(r[1]), "=r"(r[2]), "=r"(r[3]) : "r"(addr));
}

__device__ __forceinline__ void mma16816(float* c, const uint32_t* a, const uint32_t* b) {
    asm volatile(
        "mma.sync.aligned.m16n8k16.row.col.f32.bf16.bf16.f32 "
        "{%0,%1,%2,%3}, {%4,%5,%6,%7}, {%8,%9}, {%0,%1,%2,%3};"
        : "+f"(c[0]), "+f"(c[1]), "+f"(c[2]), "+f"(c[3])
        : "r"(a[0]), "r"(a[1]), "r"(a[2]), "r"(a[3]), "r"(b[0]), "r"(b[1]));
}

// fast sigmoid: 1/(1+e^-x)
__device__ __forceinline__ float fsig(float x) {
    float e = __expf(-x);
    return __fdividef(1.f, 1.f + e);
}
// fast tanh via sigmoid: 2*sig(2x)-1
__device__ __forceinline__ float ftanh(float x) {
    return 2.f * fsig(2.f * x) - 1.f;
}

// ---------------- prepack kernels ----------------
__global__ void prepack_x_kernel(const float* __restrict__ x) {
    size_t idx = (size_t)blockIdx.x * blockDim.x + threadIdx.x;
    size_t stride = (size_t)gridDim.x * blockDim.x;
    const size_t total = (size_t)B_SZ * XCOLS;
    for (size_t i = idx; i < total; i += stride) {
        float v = x[i];
        __nv_bfloat16 hi = __float2bfloat16(v);
        g_xh[i] = hi;
        g_xl[i] = __float2bfloat16(v - __bfloat162float(hi));
    }
}

__global__ void prepack_w_kernel(const float* __restrict__ W_ih,
                                 const float* __restrict__ W_hh,
                                 const float* __restrict__ b_ih,
                                 const float* __restrict__ b_hh) {
    int idx = blockIdx.x * blockDim.x + threadIdx.x;
    int stride = gridDim.x * blockDim.x;
    const int total = GATES * KTOT;
    for (int i = idx; i < total; i += stride) {
        int col = i / KTOT;
        int k   = i - col * KTOT;
        int n = col >> 2, g = col & 3;
        int row = g * HID + n;
        float v = (k < INSZ) ? W_ih[row * INSZ + k] : W_hh[row * HID + (k - INSZ)];
        __nv_bfloat16 hi = __float2bfloat16(v);
        g_Bh[i] = hi;
        g_Bl[i] = __float2bfloat16(v - __bfloat162float(hi));
    }
    for (int i = idx; i < GATES; i += stride) {
        int n = i >> 2, g = i & 3;
        int row = g * HID + n;
        g_bias[i] = b_ih[row] + b_hh[row];
    }
}

__global__ void init_state_kernel(const float* __restrict__ h0,
                                  const float* __restrict__ c0) {
    int idx = blockIdx.x * blockDim.x + threadIdx.x;
    int stride = gridDim.x * blockDim.x;
    for (int i = idx; i < B_SZ * HID; i += stride) {
        float h = h0[i];
        __nv_bfloat16 hi = __float2bfloat16(h);
        g_hh[0][i] = hi;
        g_hl[0][i] = __float2bfloat16(h - __bfloat162float(hi));
        g_c[i] = c0[i];
    }
}

// ---------------- main per-step kernel ----------------
// gates[128 x 128] = [x_t | h] @ Wpack^T over K'=1728 (bf16x3 split),
// via mma.sync m16n8k16 bf16, then fused LSTM epilogue.
__global__ __launch_bounds__(256, 1)
void lstm_step_mma(int t, int buf)
{
    extern __shared__ char smem[];
    const uint32_t sbase = smem_u32(smem);
    const int tid  = threadIdx.x;
    const int wid  = tid >> 5;
    const int lane = tid & 31;
    const int row0 = blockIdx.y * BM;   // batch base
    const int col0 = blockIdx.x * BN;   // packed gate col base
    const int nbuf = buf ^ 1;

    // warp layout: 4 (M) x 2 (N); warp tile = 32 rows x 64 cols
    const int wm = wid >> 1;            // 0..3
    const int wn = wid & 1;             // 0..1

    float* sBias = reinterpret_cast<float*>(smem + SOFF_BIAS);
    if (tid < BN) sBias[tid] = g_bias[col0 + tid];

    // ---- tile loader mapping (256 threads, 128 rows x 128B rows) ----
    const int r     = tid >> 1;                       // tile row 0..127
    const int halfe = (tid & 1) * 32;                 // element offset
    const uint32_t rowoff = (uint32_t)r * 128 + (tid & 1) * 64;

    const uint32_t sA0 = sbase + SOFF_A;
    const uint32_t sB0 = sbase + SOFF_B;

    auto load_tile = [&](int kt) {
        const int seg = kt / 9;          // 0: hi*hi, 1: lo*hi, 2: hi*lo
        const int sub = kt - seg * 9;
        const __nv_bfloat16* __restrict__ Asrc;
        size_t abase;
        if (sub == 0) {
            Asrc  = (seg == 1) ? g_xl : g_xh;
            abase = (size_t)(row0 + r) * XCOLS + (size_t)t * INSZ;
        } else {
            Asrc  = (seg == 1) ? g_hl[buf] : g_hh[buf];
            abase = (size_t)(row0 + r) * HID + (size_t)(sub - 1) * KTILE;
        }
        const __nv_bfloat16* __restrict__ Bsrc = (seg == 2) ? g_Bl : g_Bh;
        const size_t bbase = (size_t)(col0 + r) * KTOT + (size_t)sub * KTILE;

        const uint32_t bufoff = (uint32_t)(kt & 1) * 16384;
#pragma unroll
        for (int c = 0; c < 4; ++c) {
            uint32_t so = SWZ(rowoff + c * 16);
            cp16(sA0 + bufoff + so, Asrc + abase + halfe + c * 8);
            cp16(sB0 + bufoff + so, Bsrc + bbase + halfe + c * 8);
        }
        cp_commit();
    };

    // ---- fragment addressing (per-lane constants) ----
    const int lane7 = lane & 7;
    const int arow  = wm * 32 + ((lane >> 3) & 1) * 8 + lane7;  // + mf*16
    const int ach   = (lane >> 4) & 1;                          // + kk*2
    const int brow  = wn * 64 + ((lane >> 4) & 1) * 8 + lane7;  // + p*16
    const int bch   = (lane >> 3) & 1;                          // + kk*2

    float acc[2][8][4];
#pragma unroll
    for (int mf = 0; mf < 2; ++mf)
#pragma unroll
        for (int nf = 0; nf < 8; ++nf)
#pragma unroll
            for (int q = 0; q < 4; ++q) acc[mf][nf][q] = 0.f;

    load_tile(0);

    for (int kt = 0; kt < NKT; ++kt) {
        if (kt < NKT - 1) { load_tile(kt + 1); cp_wait<1>(); }
        else              { cp_wait<0>(); }
        __syncthreads();

        const uint32_t sA = sA0 + (uint32_t)(kt & 1) * 16384;
        const uint32_t sB = sB0 + (uint32_t)(kt & 1) * 16384;

#pragma unroll
        for (int kk = 0; kk < 4; ++kk) {
            uint32_t af[2][4];
#pragma unroll
            for (int mf = 0; mf < 2; ++mf)
                ldsm4(af[mf], sA + SWZ((uint32_t)(arow + mf * 16) * 128
                                       + (uint32_t)(kk * 2 + ach) * 16));
            uint32_t bf[8][2];
#pragma unroll
            for (int p = 0; p < 4; ++p) {
                uint32_t rr[4];
                ldsm4(rr, sB + SWZ((uint32_t)(brow + p * 16) * 128
                                   + (uint32_t)(kk * 2 + bch) * 16));
                bf[p * 2 + 0][0] = rr[0]; bf[p * 2 + 0][1] = rr[1];
                bf[p * 2 + 1][0] = rr[2]; bf[p * 2 + 1][1] = rr[3];
            }
#pragma unroll
            for (int mf = 0; mf < 2; ++mf)
#pragma unroll
                for (int nf = 0; nf < 8; ++nf)
                    mma16816(acc[mf][nf], af[mf], bf[nf]);
        }
        __syncthreads();
    }

    // ---------------- epilogue ----------------
    // acc frag (mf,nf): c0,c1 = (row base+lane/4,     col cb+0/1)
    //                   c2,c3 = (row base+lane/4 + 8, col cb+0/1)
    // cb = wn*64 + nf*8 + (lane%4)*2
    const int q    = lane & 3;
    const bool ev  = (q & 1) == 0;          // even q holds (i,f); odd holds (g,o)
    const int rb   = row0 + wm * 32 + (lane >> 2);

#pragma unroll
    for (int mf = 0; mf < 2; ++mf) {
#pragma unroll
        for (int nf = 0; nf < 8; ++nf) {
            const int cb = wn * 64 + nf * 8 + q * 2;
            const float b0 = sBias[cb], b1 = sBias[cb + 1];
#pragma unroll
            for (int rs = 0; rs < 2; ++rs) {
                float v0 = acc[mf][nf][rs * 2 + 0] + b0;
                float v1 = acc[mf][nf][rs * 2 + 1] + b1;
                // even lane: x0=sig(i), x1=sig(f); odd lane: x0=tanh(g), x1=sig(o)
                float x0 = ev ? fsig(v0) : ftanh(v0);
                float x1 = fsig(v1);
                float y0 = __shfl_xor_sync(0xffffffffu, x0, 1);
                float y1 = __shfl_xor_sync(0xffffffffu, x1, 1);
                if (ev) {
                    const int n   = (col0 + cb) >> 2;
                    const int b   = rb + mf * 16 + rs * 8;
                    const size_t idx = (size_t)b * HID + n;
                    float cn = x1 * g_c[idx] + x0 * y0;   // sf*c + si*tg
                    g_c[idx] = cn;
                    float hn = y1 * ftanh(cn);            // so * tanh(cn)
                    __nv_bfloat16 hhi = __float2bfloat16(hn);
                    g_hh[nbuf][idx] = hhi;
                    g_hl[nbuf][idx] = __float2bfloat16(hn - __bfloat162float(hhi));
                }
            }
        }
    }
}

// ---------------- final linear ----------------
__global__ void final_linear_kernel(const float* __restrict__ W_lin,
                                    const float* __restrict__ b_lin,
                                    float* __restrict__ out, int buf)
{
    int b = blockIdx.x;
    int w = threadIdx.y;      // 0..9
    int lane = threadIdx.x;   // 0..31
    const __nv_bfloat16* hh = g_hh[buf] + (size_t)b * HID;
    const __nv_bfloat16* hl = g_hl[buf] + (size_t)b * HID;
    const float* wl = W_lin + (size_t)w * HID;
    float s = 0.f;
#pragma unroll 4
    for (int k = lane; k < HID; k += 32) {
        float h = __bfloat162float(hh[k]) + __bfloat162float(hl[k]);
        s += h * wl[k];
    }
#pragma unroll
    for (int off = 16; off; off >>= 1)
        s += __shfl_down_sync(0xffffffffu, s, off);
    if (lane == 0)
        out[b * 10 + w] = s + b_lin[w];
}

// ---------------- launch ----------------
extern "C" void kernel_launch(void* const* d_in, const int* in_sizes, int n_in,
                              void* d_out, int out_size)
{
    const float* x     = (const float*)d_in[0];
    const float* h0    = (const float*)d_in[1];
    const float* c0    = (const float*)d_in[2];
    const float* W_ih  = (const float*)d_in[3];
    const float* W_hh  = (const float*)d_in[4];
    const float* b_ih  = (const float*)d_in[5];
    const float* b_hh  = (const float*)d_in[6];
    const float* W_lin = (const float*)d_in[7];
    const float* b_lin = (const float*)d_in[8];
    float* out = (float*)d_out;

    cudaFuncSetAttribute(lstm_step_mma,
                         cudaFuncAttributeMaxDynamicSharedMemorySize, SMEM_TOTAL);

    prepack_x_kernel<<<2048, 256>>>(x);
    prepack_w_kernel<<<1024, 256>>>(W_ih, W_hh, b_ih, b_hh);
    init_state_kernel<<<512, 512>>>(h0, c0);

    dim3 grid(GATES / BN, B_SZ / BM);   // 16 x 8 = 128 CTAs
    for (int t = 0; t < TSTEPS; ++t) {
        lstm_step_mma<<<grid, 256, SMEM_TOTAL>>>(t, t & 1);
    }

    final_linear_kernel<<<B_SZ, dim3(32, 10)>>>(W_lin, b_lin, out, TSTEPS & 1);
}

// round 4
// speedup vs baseline: 2.3913x; 1.5590x over previous
#include <cuda_runtime.h>
#include <cuda_bf16.h>
#include <math.h>
#include <stdint.h>

// ---------------- problem constants ----------------
#define B_SZ   1024
#define HID    512
#define INSZ   64
#define TSTEPS 256
#define GATES  2048              // 4*HID
#define KTOT   576               // INSZ + HID
#define XCOLS  (TSTEPS * INSZ)   // 16384

// ---------------- GEMM tiling ----------------
#define BM 128
#define BN 128
#define KTILE 64                 // 64 bf16 = 128 bytes per row
#define NJOBS 18                 // 9 A_hi jobs (2 passes each) + 9 A_lo jobs (1 pass)
#define NCTA 128

// SW128 swizzle (Swizzle<3,4,3>) on byte offsets within a tile
#define SWZ(o) ((o) ^ (((o) >> 3) & 0x70))

// dynamic smem layout (all tile bases 1024-aligned)
#define SOFF_BIAS  0                         // 128 floats
#define SOFF_BH    1024                      // 9 x 16384 = 147456
#define SOFF_A     (1024 + 147456)           // 2 x 16384 (148480)
#define SOFF_BL    (SOFF_A + 32768)          // 2 x 16384 (181248)
#define SMEM_TOTAL (SOFF_BL + 32768)         // 214016

// ---------------- device scratch (no allocs allowed) ----------------
static __device__ __align__(256) __nv_bfloat16 g_xh[(size_t)B_SZ * XCOLS];
static __device__ __align__(256) __nv_bfloat16 g_xl[(size_t)B_SZ * XCOLS];
static __device__ __align__(256) __nv_bfloat16 g_Bh[GATES * KTOT];   // packed col = n*4+g
static __device__ __align__(256) __nv_bfloat16 g_Bl[GATES * KTOT];
static __device__ float        g_bias[GATES];
static __device__ __align__(256) __nv_bfloat16 g_hh[2][B_SZ * HID];
static __device__ __align__(256) __nv_bfloat16 g_hl[2][B_SZ * HID];
static __device__ unsigned long long g_ticket;   // grid barrier; zero-init; stays ≡0 mod 128

// ---------------- PTX helpers ----------------
__device__ __forceinline__ uint32_t smem_u32(const void* p) {
    uint32_t a;
    asm("{ .reg .u64 t; cvta.to.shared.u64 t, %1; cvt.u32.u64 %0, t; }"
        : "=r"(a) : "l"(p));
    return a;
}

__device__ __forceinline__ void cp16(uint32_t dst, const void* src) {
    asm volatile("cp.async.cg.shared.global [%0], [%1], 16;"
                 :: "r"(dst), "l"(src));
}
__device__ __forceinline__ void cp_commit() {
    asm volatile("cp.async.commit_group;" ::: "memory");
}
template<int N>
__device__ __forceinline__ void cp_wait() {
    asm volatile("cp.async.wait_group %0;" :: "n"(N) : "memory");
}

__device__ __forceinline__ void ldsm4(uint32_t* r, uint32_t addr) {
    asm volatile("ldmatrix.sync.aligned.m8n8.x4.shared.b16 {%0,%1,%2,%3}, [%4];"
                 : "=r"(r[0]), "=r"(r[1]), "=r"(r[2]), "=r"(r[3]) : "r"(addr));
}

__device__ __forceinline__ void mma16816(float* c, const uint32_t* a, const uint32_t* b) {
    asm volatile(
        "mma.sync.aligned.m16n8k16.row.col.f32.bf16.bf16.f32 "
        "{%0,%1,%2,%3}, {%4,%5,%6,%7}, {%8,%9}, {%0,%1,%2,%3};"
        : "+f"(c[0]), "+f"(c[1]), "+f"(c[2]), "+f"(c[3])
        : "r"(a[0]), "r"(a[1]), "r"(a[2]), "r"(a[3]), "r"(b[0]), "r"(b[1]));
}

__device__ __forceinline__ float fsig(float x) {
    float e = __expf(-x);
    return __fdividef(1.f, 1.f + e);
}
__device__ __forceinline__ float ftanh(float x) {
    return 2.f * fsig(2.f * x) - 1.f;
}

// grid-wide barrier: monotonic ticket counter (persists across launches;
// each launch adds exactly TSTEPS*NCTA arrivals, so base stays ≡ 0 mod NCTA)
__device__ __forceinline__ void grid_sync() {
    __syncthreads();
    if (threadIdx.x == 0) {
        __threadfence();
        unsigned long long v = atomicAdd(&g_ticket, 1ULL);
        unsigned long long target = (v / (unsigned long long)NCTA + 1ULL) * (unsigned long long)NCTA;
        unsigned long long cur;
        do {
            asm volatile("ld.acquire.gpu.u64 %0, [%1];" : "=l"(cur) : "l"(&g_ticket));
        } while (cur < target);
    }
    __syncthreads();
}

// ---------------- prepack kernels ----------------
__global__ void prepack_x_kernel(const float* __restrict__ x) {
    size_t idx = (size_t)blockIdx.x * blockDim.x + threadIdx.x;
    size_t stride = (size_t)gridDim.x * blockDim.x;
    const size_t total = (size_t)B_SZ * XCOLS;
    for (size_t i = idx; i < total; i += stride) {
        float v = x[i];
        __nv_bfloat16 hi = __float2bfloat16(v);
        g_xh[i] = hi;
        g_xl[i] = __float2bfloat16(v - __bfloat162float(hi));
    }
}

__global__ void prepack_w_kernel(const float* __restrict__ W_ih,
                                 const float* __restrict__ W_hh,
                                 const float* __restrict__ b_ih,
                                 const float* __restrict__ b_hh) {
    int idx = blockIdx.x * blockDim.x + threadIdx.x;
    int stride = gridDim.x * blockDim.x;
    const int total = GATES * KTOT;
    for (int i = idx; i < total; i += stride) {
        int col = i / KTOT;
        int k   = i - col * KTOT;
        int n = col >> 2, g = col & 3;
        int row = g * HID + n;
        float v = (k < INSZ) ? W_ih[row * INSZ + k] : W_hh[row * HID + (k - INSZ)];
        __nv_bfloat16 hi = __float2bfloat16(v);
        g_Bh[i] = hi;
        g_Bl[i] = __float2bfloat16(v - __bfloat162float(hi));
    }
    for (int i = idx; i < GATES; i += stride) {
        int n = i >> 2, g = i & 3;
        int row = g * HID + n;
        g_bias[i] = b_ih[row] + b_hh[row];
    }
}

__global__ void init_state_kernel(const float* __restrict__ h0) {
    int idx = blockIdx.x * blockDim.x + threadIdx.x;
    int stride = gridDim.x * blockDim.x;
    for (int i = idx; i < B_SZ * HID; i += stride) {
        float h = h0[i];
        __nv_bfloat16 hi = __float2bfloat16(h);
        g_hh[0][i] = hi;
        g_hl[0][i] = __float2bfloat16(h - __bfloat162float(hi));
    }
}

// ---------------- persistent LSTM kernel ----------------
// All 256 steps in one launch. B_hi resident in smem; B_lo streamed;
// A_hi tiles reused across the B_hi and B_lo passes; c in registers.
__global__ __launch_bounds__(256, 1)
void lstm_persistent(const float* __restrict__ c0g)
{
    extern __shared__ char smem[];
    const uint32_t sbase = smem_u32(smem);
    const int tid  = threadIdx.x;
    const int wid  = tid >> 5;
    const int lane = tid & 31;
    const int row0 = blockIdx.y * BM;   // batch base
    const int col0 = blockIdx.x * BN;   // packed gate col base
    const int wm = wid >> 1;            // 0..3
    const int wn = wid & 1;             // 0..1

    float* sBias = reinterpret_cast<float*>(smem + SOFF_BIAS);
    if (tid < BN) sBias[tid] = g_bias[col0 + tid];

    // loader mapping: 256 threads cover 128 rows x 128B
    const int r     = tid >> 1;
    const int halfe = (tid & 1) * 32;
    const uint32_t rowoff = (uint32_t)r * 128 + (tid & 1) * 64;

    // ---- load resident B_hi (9 chunks, 147KB) ----
    {
        const size_t bb = (size_t)(col0 + r) * KTOT;
        for (int sub = 0; sub < 9; ++sub) {
            uint32_t dst = sbase + SOFF_BH + sub * 16384;
#pragma unroll
            for (int c = 0; c < 4; ++c)
                cp16(dst + SWZ(rowoff + c * 16), g_Bh + bb + sub * KTILE + halfe + c * 8);
        }
        cp_commit();
    }

    // ---- c state in registers (mapping is step-invariant) ----
    const int q  = lane & 3;
    const bool ev = (q & 1) == 0;
    float creg[2][8][2];
#pragma unroll
    for (int mf = 0; mf < 2; ++mf)
#pragma unroll
        for (int nf = 0; nf < 8; ++nf)
#pragma unroll
            for (int rs = 0; rs < 2; ++rs) {
                int cb = wn * 64 + nf * 8 + q * 2;
                int n  = (col0 + cb) >> 2;
                int b  = row0 + wm * 32 + (lane >> 2) + mf * 16 + rs * 8;
                creg[mf][nf][rs] = c0g[(size_t)b * HID + n];
            }

    cp_wait<0>();
    __syncthreads();

    // fragment addressing constants
    const int lane7 = lane & 7;
    const int arow  = wm * 32 + ((lane >> 3) & 1) * 8 + lane7;
    const int ach   = (lane >> 4) & 1;
    const int brow  = wn * 64 + ((lane >> 4) & 1) * 8 + lane7;
    const int bch   = (lane >> 3) & 1;

    const uint32_t sA0  = sbase + SOFF_A;
    const uint32_t sBL0 = sbase + SOFF_BL;

    for (int t = 0; t < TSTEPS; ++t) {
        const int buf  = t & 1;
        const int nbuf = buf ^ 1;

        float acc[2][8][4];
#pragma unroll
        for (int mf = 0; mf < 2; ++mf)
#pragma unroll
            for (int nf = 0; nf < 8; ++nf)
#pragma unroll
                for (int u = 0; u < 4; ++u) acc[mf][nf][u] = 0.f;

        // job j: j<9 -> A_hi[j] x (B_hi[j], B_lo[j]); j>=9 -> A_lo[j-9] x B_hi[j-9]
        auto issue_job = [&](int j) {
            const int sub = (j < 9) ? j : j - 9;
            const bool hi = (j < 9);
            const __nv_bfloat16* __restrict__ Asrc;
            size_t abase;
            if (sub == 0) {
                Asrc  = hi ? g_xh : g_xl;
                abase = (size_t)(row0 + r) * XCOLS + (size_t)t * INSZ;
            } else {
                Asrc  = hi ? g_hh[buf] : g_hl[buf];
                abase = (size_t)(row0 + r) * HID + (size_t)(sub - 1) * KTILE;
            }
            const uint32_t bo = (uint32_t)(j & 1) * 16384;
#pragma unroll
            for (int c = 0; c < 4; ++c)
                cp16(sA0 + bo + SWZ(rowoff + c * 16), Asrc + abase + halfe + c * 8);
            if (hi) {
                const size_t bbase = (size_t)(col0 + r) * KTOT + (size_t)sub * KTILE;
#pragma unroll
                for (int c = 0; c < 4; ++c)
                    cp16(sBL0 + bo + SWZ(rowoff + c * 16), g_Bl + bbase + halfe + c * 8);
            }
        };

        issue_job(0); cp_commit();
        issue_job(1); cp_commit();

        for (int j = 0; j < NJOBS; ++j) {
            cp_wait<1>();
            __syncthreads();

            const uint32_t sA = sA0 + (uint32_t)(j & 1) * 16384;
            const int sub = (j < 9) ? j : j - 9;

            // cache A fragments (reused by both passes)
            uint32_t af[4][2][4];
#pragma unroll
            for (int kk = 0; kk < 4; ++kk)
#pragma unroll
                for (int mf = 0; mf < 2; ++mf)
                    ldsm4(af[kk][mf], sA + SWZ((uint32_t)(arow + mf * 16) * 128
                                               + (uint32_t)(kk * 2 + ach) * 16));

            // pass 1: resident B_hi
            {
                const uint32_t sB = sbase + SOFF_BH + (uint32_t)sub * 16384;
#pragma unroll
                for (int kk = 0; kk < 4; ++kk) {
                    uint32_t bf[8][2];
#pragma unroll
                    for (int p = 0; p < 4; ++p) {
                        uint32_t rr[4];
                        ldsm4(rr, sB + SWZ((uint32_t)(brow + p * 16) * 128
                                           + (uint32_t)(kk * 2 + bch) * 16));
                        bf[p * 2 + 0][0] = rr[0]; bf[p * 2 + 0][1] = rr[1];
                        bf[p * 2 + 1][0] = rr[2]; bf[p * 2 + 1][1] = rr[3];
                    }
#pragma unroll
                    for (int mf = 0; mf < 2; ++mf)
#pragma unroll
                        for (int nf = 0; nf < 8; ++nf)
                            mma16816(acc[mf][nf], af[kk][mf], bf[nf]);
                }
            }
            // pass 2: streamed B_lo (A_hi jobs only)
            if (j < 9) {
                const uint32_t sB = sBL0 + (uint32_t)(j & 1) * 16384;
#pragma unroll
                for (int kk = 0; kk < 4; ++kk) {
                    uint32_t bf[8][2];
#pragma unroll
                    for (int p = 0; p < 4; ++p) {
                        uint32_t rr[4];
                        ldsm4(rr, sB + SWZ((uint32_t)(brow + p * 16) * 128
                                           + (uint32_t)(kk * 2 + bch) * 16));
                        bf[p * 2 + 0][0] = rr[0]; bf[p * 2 + 0][1] = rr[1];
                        bf[p * 2 + 1][0] = rr[2]; bf[p * 2 + 1][1] = rr[3];
                    }
#pragma unroll
                    for (int mf = 0; mf < 2; ++mf)
#pragma unroll
                        for (int nf = 0; nf < 8; ++nf)
                            mma16816(acc[mf][nf], af[kk][mf], bf[nf]);
                }
            }

            __syncthreads();
            if (j + 2 < NJOBS) issue_job(j + 2);
            cp_commit();
        }

        // ---- fused LSTM epilogue ----
#pragma unroll
        for (int mf = 0; mf < 2; ++mf) {
#pragma unroll
            for (int nf = 0; nf < 8; ++nf) {
                const int cb = wn * 64 + nf * 8 + q * 2;
                const float b0 = sBias[cb], b1 = sBias[cb + 1];
#pragma unroll
                for (int rs = 0; rs < 2; ++rs) {
                    float v0 = acc[mf][nf][rs * 2 + 0] + b0;
                    float v1 = acc[mf][nf][rs * 2 + 1] + b1;
                    // even lanes: x0=sig(i), x1=sig(f); odd lanes: x0=tanh(g), x1=sig(o)
                    float x0 = ev ? fsig(v0) : ftanh(v0);
                    float x1 = fsig(v1);
                    float y0 = __shfl_xor_sync(0xffffffffu, x0, 1);
                    float y1 = __shfl_xor_sync(0xffffffffu, x1, 1);
                    if (ev) {
                        const int n = (col0 + cb) >> 2;
                        const int b = row0 + wm * 32 + (lane >> 2) + mf * 16 + rs * 8;
                        const size_t idx = (size_t)b * HID + n;
                        float cn = x1 * creg[mf][nf][rs] + x0 * y0;   // f*c + i*g
                        creg[mf][nf][rs] = cn;
                        float hn = y1 * ftanh(cn);                    // o * tanh(c)
                        __nv_bfloat16 hhi = __float2bfloat16(hn);
                        g_hh[nbuf][idx] = hhi;
                        g_hl[nbuf][idx] = __float2bfloat16(hn - __bfloat162float(hhi));
                    }
                }
            }
        }

        grid_sync();
    }
}

// ---------------- final linear ----------------
__global__ void final_linear_kernel(const float* __restrict__ W_lin,
                                    const float* __restrict__ b_lin,
                                    float* __restrict__ out, int buf)
{
    int b = blockIdx.x;
    int w = threadIdx.y;      // 0..9
    int lane = threadIdx.x;   // 0..31
    const __nv_bfloat16* hh = g_hh[buf] + (size_t)b * HID;
    const __nv_bfloat16* hl = g_hl[buf] + (size_t)b * HID;
    const float* wl = W_lin + (size_t)w * HID;
    float s = 0.f;
#pragma unroll 4
    for (int k = lane; k < HID; k += 32) {
        float h = __bfloat162float(hh[k]) + __bfloat162float(hl[k]);
        s += h * wl[k];
    }
#pragma unroll
    for (int off = 16; off; off >>= 1)
        s += __shfl_down_sync(0xffffffffu, s, off);
    if (lane == 0)
        out[b * 10 + w] = s + b_lin[w];
}

// ---------------- launch ----------------
extern "C" void kernel_launch(void* const* d_in, const int* in_sizes, int n_in,
                              void* d_out, int out_size)
{
    const float* x     = (const float*)d_in[0];
    const float* h0    = (const float*)d_in[1];
    const float* c0    = (const float*)d_in[2];
    const float* W_ih  = (const float*)d_in[3];
    const float* W_hh  = (const float*)d_in[4];
    const float* b_ih  = (const float*)d_in[5];
    const float* b_hh  = (const float*)d_in[6];
    const float* W_lin = (const float*)d_in[7];
    const float* b_lin = (const float*)d_in[8];
    float* out = (float*)d_out;

    cudaFuncSetAttribute(lstm_persistent,
                         cudaFuncAttributeMaxDynamicSharedMemorySize, SMEM_TOTAL);

    prepack_x_kernel<<<2048, 256>>>(x);
    prepack_w_kernel<<<1024, 256>>>(W_ih, W_hh, b_ih, b_hh);
    init_state_kernel<<<512, 512>>>(h0);

    dim3 grid(GATES / BN, B_SZ / BM);   // 16 x 8 = 128 CTAs (all resident)
    lstm_persistent<<<grid, 256, SMEM_TOTAL>>>(c0);

    // 256 steps -> final h is in buffer (TSTEPS & 1) = 0
    final_linear_kernel<<<B_SZ, dim3(32, 10)>>>(W_lin, b_lin, out, 0);
}

// round 5
// speedup vs baseline: 2.8053x; 1.1732x over previous
#include <cuda_runtime.h>
#include <cuda_bf16.h>
#include <math.h>
#include <stdint.h>

// ---------------- problem constants ----------------
#define B_SZ   1024
#define HID    512
#define INSZ   64
#define TSTEPS 256
#define GATES  2048              // 4*HID
#define KTOT   576               // INSZ + HID
#define XCOLS  (TSTEPS * INSZ)   // 16384

// ---------------- GEMM tiling ----------------
#define BM 128
#define BN 128
#define KTILE 64                 // 64 bf16 = 128 bytes per row
#define NJOBS 18                 // 9 A_hi jobs (2 passes) + 9 A_lo jobs (1 pass)
#define NROWCTA 16               // CTAs per row group (same blockIdx.y)

// SW128 swizzle (Swizzle<3,4,3>) on byte offsets within a tile
#define SWZ(o) ((o) ^ (((o) >> 3) & 0x70))

// dynamic smem layout (all tile bases 1024-aligned)
#define SOFF_BIAS  0                         // 128 floats
#define SOFF_BH    1024                      // 9 x 16384 = 147456
#define SOFF_A     (1024 + 147456)           // 2 x 16384
#define SOFF_BL    (SOFF_A + 32768)          // 2 x 16384
#define SMEM_TOTAL (SOFF_BL + 32768)         // 214016

// ---------------- device scratch (no allocs allowed) ----------------
static __device__ __align__(256) __nv_bfloat16 g_xh[(size_t)B_SZ * XCOLS];
static __device__ __align__(256) __nv_bfloat16 g_xl[(size_t)B_SZ * XCOLS];
static __device__ __align__(256) __nv_bfloat16 g_Bh[GATES * KTOT];   // packed col = n*4+g
static __device__ __align__(256) __nv_bfloat16 g_Bl[GATES * KTOT];
static __device__ float        g_bias[GATES];
static __device__ __align__(256) __nv_bfloat16 g_hh[2][B_SZ * HID];
static __device__ __align__(256) __nv_bfloat16 g_hl[2][B_SZ * HID];
// per-row-group monotonic tickets, 128B apart to avoid L2 line sharing
static __device__ unsigned long long g_row_ticket[8 * 16];

// ---------------- PTX helpers ----------------
__device__ __forceinline__ uint32_t smem_u32(const void* p) {
    uint32_t a;
    asm("{ .reg .u64 t; cvta.to.shared.u64 t, %1; cvt.u32.u64 %0, t; }"
        : "=r"(a) : "l"(p));
    return a;
}

__device__ __forceinline__ void cp16(uint32_t dst, const void* src) {
    asm volatile("cp.async.cg.shared.global [%0], [%1], 16;"
                 :: "r"(dst), "l"(src));
}
__device__ __forceinline__ void cp_commit() {
    asm volatile("cp.async.commit_group;" ::: "memory");
}
template<int N>
__device__ __forceinline__ void cp_wait() {
    asm volatile("cp.async.wait_group %0;" :: "n"(N) : "memory");
}

__device__ __forceinline__ void ldsm4(uint32_t* r, uint32_t addr) {
    asm volatile("ldmatrix.sync.aligned.m8n8.x4.shared.b16 {%0,%1,%2,%3}, [%4];"
                 : "=r"(r[0]), "=r"(r[1]), "=r"(r[2]), "=r"(r[3]) : "r"(addr));
}

__device__ __forceinline__ void mma16816(float* c, const uint32_t* a, const uint32_t* b) {
    asm volatile(
        "mma.sync.aligned.m16n8k16.row.col.f32.bf16.bf16.f32 "
        "{%0,%1,%2,%3}, {%4,%5,%6,%7}, {%8,%9}, {%0,%1,%2,%3};"
        : "+f"(c[0]), "+f"(c[1]), "+f"(c[2]), "+f"(c[3])
        : "r"(a[0]), "r"(a[1]), "r"(a[2]), "r"(a[3]), "r"(b[0]), "r"(b[1]));
}

__device__ __forceinline__ float fsig(float x) {
    float e = __expf(-x);
    return __fdividef(1.f, 1.f + e);
}
__device__ __forceinline__ float ftanh(float x) {
    return 2.f * fsig(2.f * x) - 1.f;
}

// row-group barrier: 16 CTAs sharing blockIdx.y. Monotonic ticket; each
// launch adds (TSTEPS-1)*16 arrivals per counter -> stays ≡ 0 mod 16.
__device__ __forceinline__ void row_sync(int ygrp) {
    __syncthreads();
    if (threadIdx.x == 0) {
        __threadfence();
        unsigned long long* p = &g_row_ticket[ygrp * 16];
        unsigned long long v = atomicAdd(p, 1ULL);
        unsigned long long target = (v / (unsigned long long)NROWCTA + 1ULL)
                                    * (unsigned long long)NROWCTA;
        unsigned long long cur;
        do {
            asm volatile("ld.acquire.gpu.u64 %0, [%1];" : "=l"(cur) : "l"(p));
        } while (cur < target);
    }
    __syncthreads();
}

// ---------------- prepack kernels ----------------
__global__ void prepack_x_kernel(const float* __restrict__ x) {
    size_t idx = (size_t)blockIdx.x * blockDim.x + threadIdx.x;
    size_t stride = (size_t)gridDim.x * blockDim.x;
    const size_t total = (size_t)B_SZ * XCOLS;
    for (size_t i = idx; i < total; i += stride) {
        float v = x[i];
        __nv_bfloat16 hi = __float2bfloat16(v);
        g_xh[i] = hi;
        g_xl[i] = __float2bfloat16(v - __bfloat162float(hi));
    }
}

__global__ void prepack_w_kernel(const float* __restrict__ W_ih,
                                 const float* __restrict__ W_hh,
                                 const float* __restrict__ b_ih,
                                 const float* __restrict__ b_hh) {
    int idx = blockIdx.x * blockDim.x + threadIdx.x;
    int stride = gridDim.x * blockDim.x;
    const int total = GATES * KTOT;
    for (int i = idx; i < total; i += stride) {
        int col = i / KTOT;
        int k   = i - col * KTOT;
        int n = col >> 2, g = col & 3;
        int row = g * HID + n;
        float v = (k < INSZ) ? W_ih[row * INSZ + k] : W_hh[row * HID + (k - INSZ)];
        __nv_bfloat16 hi = __float2bfloat16(v);
        g_Bh[i] = hi;
        g_Bl[i] = __float2bfloat16(v - __bfloat162float(hi));
    }
    for (int i = idx; i < GATES; i += stride) {
        int n = i >> 2, g = i & 3;
        int row = g * HID + n;
        g_bias[i] = b_ih[row] + b_hh[row];
    }
}

__global__ void init_state_kernel(const float* __restrict__ h0) {
    int idx = blockIdx.x * blockDim.x + threadIdx.x;
    int stride = gridDim.x * blockDim.x;
    for (int i = idx; i < B_SZ * HID; i += stride) {
        float h = h0[i];
        __nv_bfloat16 hi = __float2bfloat16(h);
        g_hh[0][i] = hi;
        g_hl[0][i] = __float2bfloat16(h - __bfloat162float(hi));
    }
}

// ---------------- persistent LSTM kernel (512 threads) ----------------
__global__ __launch_bounds__(512, 1)
void lstm_persistent(const float* __restrict__ c0g)
{
    extern __shared__ char smem[];
    const uint32_t sbase = smem_u32(smem);
    const int tid  = threadIdx.x;
    const int wid  = tid >> 5;
    const int lane = tid & 31;
    const int row0 = blockIdx.y * BM;   // batch base
    const int col0 = blockIdx.x * BN;   // packed gate col base
    const int wm = wid & 3;             // 0..3 (M)
    const int wn = wid >> 2;            // 0..3 (N)

    float* sBias = reinterpret_cast<float*>(smem + SOFF_BIAS);
    if (tid < BN) sBias[tid] = g_bias[col0 + tid];

    // loader mapping: 512 threads cover 128 rows x 128B (32B per thread)
    const int r     = tid >> 2;                       // tile row 0..127
    const int quart = tid & 3;                        // 0..3 (16-elem groups)
    const uint32_t rowoff = (uint32_t)r * 128 + (uint32_t)quart * 32;

    // ---- load resident B_hi (9 chunks, 147KB) ----
    {
        const size_t bb = (size_t)(col0 + r) * KTOT + (size_t)quart * 16;
        for (int sub = 0; sub < 9; ++sub) {
            uint32_t dst = sbase + SOFF_BH + sub * 16384;
#pragma unroll
            for (int c = 0; c < 2; ++c)
                cp16(dst + SWZ(rowoff + c * 16), g_Bh + bb + sub * KTILE + c * 8);
        }
        cp_commit();
    }

    // ---- c state in registers ----
    const int q  = lane & 3;
    const bool ev = (q & 1) == 0;
    float creg[2][4][2];
#pragma unroll
    for (int mf = 0; mf < 2; ++mf)
#pragma unroll
        for (int nf = 0; nf < 4; ++nf)
#pragma unroll
            for (int rs = 0; rs < 2; ++rs) {
                int cb = wn * 32 + nf * 8 + q * 2;
                int n  = (col0 + cb) >> 2;
                int b  = row0 + wm * 32 + (lane >> 2) + mf * 16 + rs * 8;
                creg[mf][nf][rs] = c0g[(size_t)b * HID + n];
            }

    cp_wait<0>();
    __syncthreads();

    // fragment addressing constants
    const int lane7 = lane & 7;
    const int arow  = wm * 32 + ((lane >> 3) & 1) * 8 + lane7;   // + mf*16
    const int ach   = (lane >> 4) & 1;
    const int brow  = wn * 32 + ((lane >> 4) & 1) * 8 + lane7;   // + p*16
    const int bch   = (lane >> 3) & 1;

    const uint32_t sA0  = sbase + SOFF_A;
    const uint32_t sBL0 = sbase + SOFF_BL;

    for (int t = 0; t < TSTEPS; ++t) {
        const int buf  = t & 1;
        const int nbuf = buf ^ 1;

        float acc[2][4][4];
#pragma unroll
        for (int mf = 0; mf < 2; ++mf)
#pragma unroll
            for (int nf = 0; nf < 4; ++nf)
#pragma unroll
                for (int u = 0; u < 4; ++u) acc[mf][nf][u] = 0.f;

        // job j: j<9 -> A_hi[j] x (B_hi[j] resident, B_lo[j] streamed);
        //        j>=9 -> A_lo[j-9] x B_hi[j-9] resident
        auto issue_job = [&](int j) {
            const int sub = (j < 9) ? j : j - 9;
            const bool hi = (j < 9);
            const __nv_bfloat16* __restrict__ Asrc;
            size_t abase;
            if (sub == 0) {
                Asrc  = hi ? g_xh : g_xl;
                abase = (size_t)(row0 + r) * XCOLS + (size_t)t * INSZ;
            } else {
                Asrc  = hi ? g_hh[buf] : g_hl[buf];
                abase = (size_t)(row0 + r) * HID + (size_t)(sub - 1) * KTILE;
            }
            abase += (size_t)quart * 16;
            const uint32_t bo = (uint32_t)(j & 1) * 16384;
#pragma unroll
            for (int c = 0; c < 2; ++c)
                cp16(sA0 + bo + SWZ(rowoff + c * 16), Asrc + abase + c * 8);
            if (hi) {
                const size_t bbase = (size_t)(col0 + r) * KTOT
                                     + (size_t)sub * KTILE + (size_t)quart * 16;
#pragma unroll
                for (int c = 0; c < 2; ++c)
                    cp16(sBL0 + bo + SWZ(rowoff + c * 16), g_Bl + bbase + c * 8);
            }
        };

        issue_job(0); cp_commit();
        issue_job(1); cp_commit();

        for (int j = 0; j < NJOBS; ++j) {
            cp_wait<1>();
            __syncthreads();

            const uint32_t sA = sA0 + (uint32_t)(j & 1) * 16384;
            const int sub = (j < 9) ? j : j - 9;

            // pass 1: resident B_hi
            {
                const uint32_t sB = sbase + SOFF_BH + (uint32_t)sub * 16384;
#pragma unroll
                for (int kk = 0; kk < 4; ++kk) {
                    uint32_t af[2][4];
#pragma unroll
                    for (int mf = 0; mf < 2; ++mf)
                        ldsm4(af[mf], sA + SWZ((uint32_t)(arow + mf * 16) * 128
                                               + (uint32_t)(kk * 2 + ach) * 16));
                    uint32_t bf[4][2];
#pragma unroll
                    for (int p = 0; p < 2; ++p) {
                        uint32_t rr[4];
                        ldsm4(rr, sB + SWZ((uint32_t)(brow + p * 16) * 128
                                           + (uint32_t)(kk * 2 + bch) * 16));
                        bf[p * 2 + 0][0] = rr[0]; bf[p * 2 + 0][1] = rr[1];
                        bf[p * 2 + 1][0] = rr[2]; bf[p * 2 + 1][1] = rr[3];
                    }
#pragma unroll
                    for (int mf = 0; mf < 2; ++mf)
#pragma unroll
                        for (int nf = 0; nf < 4; ++nf)
                            mma16816(acc[mf][nf], af[mf], bf[nf]);
                }
            }
            // pass 2: streamed B_lo (A_hi jobs only)
            if (j < 9) {
                const uint32_t sB = sBL0 + (uint32_t)(j & 1) * 16384;
#pragma unroll
                for (int kk = 0; kk < 4; ++kk) {
                    uint32_t af[2][4];
#pragma unroll
                    for (int mf = 0; mf < 2; ++mf)
                        ldsm4(af[mf], sA + SWZ((uint32_t)(arow + mf * 16) * 128
                                               + (uint32_t)(kk * 2 + ach) * 16));
                    uint32_t bf[4][2];
#pragma unroll
                    for (int p = 0; p < 2; ++p) {
                        uint32_t rr[4];
                        ldsm4(rr, sB + SWZ((uint32_t)(brow + p * 16) * 128
                                           + (uint32_t)(kk * 2 + bch) * 16));
                        bf[p * 2 + 0][0] = rr[0]; bf[p * 2 + 0][1] = rr[1];
                        bf[p * 2 + 1][0] = rr[2]; bf[p * 2 + 1][1] = rr[3];
                    }
#pragma unroll
                    for (int mf = 0; mf < 2; ++mf)
#pragma unroll
                        for (int nf = 0; nf < 4; ++nf)
                            mma16816(acc[mf][nf], af[mf], bf[nf]);
                }
            }

            __syncthreads();
            if (j + 2 < NJOBS) issue_job(j + 2);
            cp_commit();
        }

        // ---- fused LSTM epilogue ----
#pragma unroll
        for (int mf = 0; mf < 2; ++mf) {
#pragma unroll
            for (int nf = 0; nf < 4; ++nf) {
                const int cb = wn * 32 + nf * 8 + q * 2;
                const float b0 = sBias[cb], b1 = sBias[cb + 1];
#pragma unroll
                for (int rs = 0; rs < 2; ++rs) {
                    float v0 = acc[mf][nf][rs * 2 + 0] + b0;
                    float v1 = acc[mf][nf][rs * 2 + 1] + b1;
                    // even lanes: x0=sig(i), x1=sig(f); odd: x0=tanh(g), x1=sig(o)
                    float x0 = ev ? fsig(v0) : ftanh(v0);
                    float x1 = fsig(v1);
                    float y0 = __shfl_xor_sync(0xffffffffu, x0, 1);
                    float y1 = __shfl_xor_sync(0xffffffffu, x1, 1);
                    if (ev) {
                        const int n = (col0 + cb) >> 2;
                        const int b = row0 + wm * 32 + (lane >> 2) + mf * 16 + rs * 8;
                        const size_t idx = (size_t)b * HID + n;
                        float cn = x1 * creg[mf][nf][rs] + x0 * y0;   // f*c + i*g
                        creg[mf][nf][rs] = cn;
                        float hn = y1 * ftanh(cn);                    // o * tanh(c)
                        __nv_bfloat16 hhi = __float2bfloat16(hn);
                        g_hh[nbuf][idx] = hhi;
                        g_hl[nbuf][idx] = __float2bfloat16(hn - __bfloat162float(hhi));
                    }
                }
            }
        }

        if (t + 1 < TSTEPS) row_sync(blockIdx.y);
    }
}

// ---------------- final linear ----------------
__global__ void final_linear_kernel(const float* __restrict__ W_lin,
                                    const float* __restrict__ b_lin,
                                    float* __restrict__ out, int buf)
{
    int b = blockIdx.x;
    int w = threadIdx.y;      // 0..9
    int lane = threadIdx.x;   // 0..31
    const __nv_bfloat16* hh = g_hh[buf] + (size_t)b * HID;
    const __nv_bfloat16* hl = g_hl[buf] + (size_t)b * HID;
    const float* wl = W_lin + (size_t)w * HID;
    float s = 0.f;
#pragma unroll 4
    for (int k = lane; k < HID; k += 32) {
        float h = __bfloat162float(hh[k]) + __bfloat162float(hl[k]);
        s += h * wl[k];
    }
#pragma unroll
    for (int off = 16; off; off >>= 1)
        s += __shfl_down_sync(0xffffffffu, s, off);
    if (lane == 0)
        out[b * 10 + w] = s + b_lin[w];
}

// ---------------- launch ----------------
extern "C" void kernel_launch(void* const* d_in, const int* in_sizes, int n_in,
                              void* d_out, int out_size)
{
    const float* x     = (const float*)d_in[0];
    const float* h0    = (const float*)d_in[1];
    const float* c0    = (const float*)d_in[2];
    const float* W_ih  = (const float*)d_in[3];
    const float* W_hh  = (const float*)d_in[4];
    const float* b_ih  = (const float*)d_in[5];
    const float* b_hh  = (const float*)d_in[6];
    const float* W_lin = (const float*)d_in[7];
    const float* b_lin = (const float*)d_in[8];
    float* out = (float*)d_out;

    cudaFuncSetAttribute(lstm_persistent,
                         cudaFuncAttributeMaxDynamicSharedMemorySize, SMEM_TOTAL);

    prepack_x_kernel<<<2048, 256>>>(x);
    prepack_w_kernel<<<1024, 256>>>(W_ih, W_hh, b_ih, b_hh);
    init_state_kernel<<<512, 512>>>(h0);

    dim3 grid(GATES / BN, B_SZ / BM);   // 16 x 8 = 128 CTAs (all resident)
    lstm_persistent<<<grid, 512, SMEM_TOTAL>>>(c0);

    // 256 steps -> final h is in buffer 0
    final_linear_kernel<<<B_SZ, dim3(32, 10)>>>(W_lin, b_lin, out, 0);
}

// round 6
// speedup vs baseline: 3.0036x; 1.0707x over previous
#include <cuda_runtime.h>
#include <cuda_bf16.h>
#include <math.h>
#include <stdint.h>

// ---------------- problem constants ----------------
#define B_SZ   1024
#define HID    512
#define INSZ   64
#define TSTEPS 256
#define GATES  2048              // 4*HID
#define KTOT   576               // INSZ + HID
#define XCOLS  (TSTEPS * INSZ)   // 16384

// ---------------- GEMM tiling ----------------
#define BM 128
#define BN 128
#define KTILE 64                 // 64 bf16 = 128 bytes per row
#define NJOBS 18                 // interleaved: even=hi(sub), odd=lo(sub)
#define NROWCTA 16               // CTAs per row group (same blockIdx.y)

// SW128 swizzle (Swizzle<3,4,3>) on byte offsets within a tile
#define SWZ(o) ((o) ^ (((o) >> 3) & 0x70))

// dynamic smem layout (all tile bases 1024-aligned)
#define SOFF_BIAS  0                         // 128 floats
#define SOFF_BH    1024                      // 9 x 16384 = 147456
#define SOFF_A     (1024 + 147456)           // 3 x 16384 (triple buffer)
#define SOFF_BL    (SOFF_A + 49152)          // 2 x 16384
#define SMEM_TOTAL (SOFF_BL + 32768)         // 230400 (< 227KB cap)

// ---------------- device scratch (no allocs allowed) ----------------
static __device__ __align__(256) __nv_bfloat16 g_xh[(size_t)B_SZ * XCOLS];
static __device__ __align__(256) __nv_bfloat16 g_xl[(size_t)B_SZ * XCOLS];
static __device__ __align__(256) __nv_bfloat16 g_Bh[GATES * KTOT];   // packed col = n*4+g
static __device__ __align__(256) __nv_bfloat16 g_Bl[GATES * KTOT];
static __device__ float        g_bias[GATES];
static __device__ __align__(256) __nv_bfloat16 g_hh[2][B_SZ * HID];
static __device__ __align__(256) __nv_bfloat16 g_hl[2][B_SZ * HID];
// per-row-group tickets, 128B apart; reset to 0 at the start of every launch
static __device__ unsigned long long g_row_ticket[8 * 16];

// ---------------- PTX helpers ----------------
__device__ __forceinline__ uint32_t smem_u32(const void* p) {
    uint32_t a;
    asm("{ .reg .u64 t; cvta.to.shared.u64 t, %1; cvt.u32.u64 %0, t; }"
        : "=r"(a) : "l"(p));
    return a;
}

__device__ __forceinline__ void cp16(uint32_t dst, const void* src) {
    asm volatile("cp.async.cg.shared.global [%0], [%1], 16;"
                 :: "r"(dst), "l"(src));
}
__device__ __forceinline__ void cp_commit() {
    asm volatile("cp.async.commit_group;" ::: "memory");
}
template<int N>
__device__ __forceinline__ void cp_wait() {
    asm volatile("cp.async.wait_group %0;" :: "n"(N) : "memory");
}

__device__ __forceinline__ void ldsm4(uint32_t* r, uint32_t addr) {
    asm volatile("ldmatrix.sync.aligned.m8n8.x4.shared.b16 {%0,%1,%2,%3}, [%4];"
                 : "=r"(r[0]), "=r"(r[1]), "=r"(r[2]), "=r"(r[3]) : "r"(addr));
}

__device__ __forceinline__ void mma16816(float* c, const uint32_t* a, const uint32_t* b) {
    asm volatile(
        "mma.sync.aligned.m16n8k16.row.col.f32.bf16.bf16.f32 "
        "{%0,%1,%2,%3}, {%4,%5,%6,%7}, {%8,%9}, {%0,%1,%2,%3};"
        : "+f"(c[0]), "+f"(c[1]), "+f"(c[2]), "+f"(c[3])
        : "r"(a[0]), "r"(a[1]), "r"(a[2]), "r"(a[3]), "r"(b[0]), "r"(b[1]));
}

__device__ __forceinline__ float fsig(float x) {
    float e = __expf(-x);
    return __fdividef(1.f, 1.f + e);
}
__device__ __forceinline__ float ftanh(float x) {
    return 2.f * fsig(2.f * x) - 1.f;
}

// ---------------- prepack kernels ----------------
__global__ void prepack_x_kernel(const float* __restrict__ x) {
    size_t idx = (size_t)blockIdx.x * blockDim.x + threadIdx.x;
    size_t stride = (size_t)gridDim.x * blockDim.x;
    const size_t total = (size_t)B_SZ * XCOLS;
    for (size_t i = idx; i < total; i += stride) {
        float v = x[i];
        __nv_bfloat16 hi = __float2bfloat16(v);
        g_xh[i] = hi;
        g_xl[i] = __float2bfloat16(v - __bfloat162float(hi));
    }
}

__global__ void prepack_w_kernel(const float* __restrict__ W_ih,
                                 const float* __restrict__ W_hh,
                                 const float* __restrict__ b_ih,
                                 const float* __restrict__ b_hh) {
    int idx = blockIdx.x * blockDim.x + threadIdx.x;
    int stride = gridDim.x * blockDim.x;
    const int total = GATES * KTOT;
    for (int i = idx; i < total; i += stride) {
        int col = i / KTOT;
        int k   = i - col * KTOT;
        int n = col >> 2, g = col & 3;
        int row = g * HID + n;
        float v = (k < INSZ) ? W_ih[row * INSZ + k] : W_hh[row * HID + (k - INSZ)];
        __nv_bfloat16 hi = __float2bfloat16(v);
        g_Bh[i] = hi;
        g_Bl[i] = __float2bfloat16(v - __bfloat162float(hi));
    }
    for (int i = idx; i < GATES; i += stride) {
        int n = i >> 2, g = i & 3;
        int row = g * HID + n;
        g_bias[i] = b_ih[row] + b_hh[row];
    }
}

__global__ void init_state_kernel(const float* __restrict__ h0) {
    int idx = blockIdx.x * blockDim.x + threadIdx.x;
    int stride = gridDim.x * blockDim.x;
    for (int i = idx; i < B_SZ * HID; i += stride) {
        float h = h0[i];
        __nv_bfloat16 hi = __float2bfloat16(h);
        g_hh[0][i] = hi;
        g_hl[0][i] = __float2bfloat16(h - __bfloat162float(hi));
    }
}

__global__ void reset_tickets_kernel() {
    if (threadIdx.x < 8 * 16) g_row_ticket[threadIdx.x] = 0ULL;
}

// ---------------- persistent LSTM kernel (512 threads) ----------------
__global__ __launch_bounds__(512, 1)
void lstm_persistent(const float* __restrict__ c0g)
{
    extern __shared__ char smem[];
    const uint32_t sbase = smem_u32(smem);
    const int tid  = threadIdx.x;
    const int wid  = tid >> 5;
    const int lane = tid & 31;
    const int row0 = blockIdx.y * BM;   // batch base
    const int col0 = blockIdx.x * BN;   // packed gate col base
    const int wm = wid & 3;             // 0..3 (M)
    const int wn = wid >> 2;            // 0..3 (N)

    float* sBias = reinterpret_cast<float*>(smem + SOFF_BIAS);
    if (tid < BN) sBias[tid] = g_bias[col0 + tid];

    // loader mapping: 512 threads cover 128 rows x 128B (32B per thread)
    const int r     = tid >> 2;
    const int quart = tid & 3;
    const uint32_t rowoff = (uint32_t)r * 128 + (uint32_t)quart * 32;

    // ---- load resident B_hi (9 chunks, 147KB) ----
    {
        const size_t bb = (size_t)(col0 + r) * KTOT + (size_t)quart * 16;
        for (int sub = 0; sub < 9; ++sub) {
            uint32_t dst = sbase + SOFF_BH + sub * 16384;
#pragma unroll
            for (int c = 0; c < 2; ++c)
                cp16(dst + SWZ(rowoff + c * 16), g_Bh + bb + sub * KTILE + c * 8);
        }
        cp_commit();
    }

    // ---- c state in registers ----
    const int q  = lane & 3;
    const bool ev = (q & 1) == 0;
    float creg[2][4][2];
#pragma unroll
    for (int mf = 0; mf < 2; ++mf)
#pragma unroll
        for (int nf = 0; nf < 4; ++nf)
#pragma unroll
            for (int rs = 0; rs < 2; ++rs) {
                int cb = wn * 32 + nf * 8 + q * 2;
                int n  = (col0 + cb) >> 2;
                int b  = row0 + wm * 32 + (lane >> 2) + mf * 16 + rs * 8;
                creg[mf][nf][rs] = c0g[(size_t)b * HID + n];
            }

    cp_wait<0>();
    __syncthreads();

    // fragment addressing constants
    const int lane7 = lane & 7;
    const int arow  = wm * 32 + ((lane >> 3) & 1) * 8 + lane7;   // + mf*16
    const int ach   = (lane >> 4) & 1;
    const int brow  = wn * 32 + ((lane >> 4) & 1) * 8 + lane7;   // + p*16
    const int bch   = (lane >> 3) & 1;

    const uint32_t sA0  = sbase + SOFF_A;
    const uint32_t sBL0 = sbase + SOFF_BL;

    // job jid: even = hi(sub=jid/2): A_hi x (B_hi + B_lo); odd = lo: A_lo x B_hi
    // A buffer = jid % 3 (triple); BL buffer = (jid/2) & 1 (double).
    auto issue_job = [&](int jid, int t, int buf) {
        const int sub = jid >> 1;
        const bool hi = (jid & 1) == 0;
        const __nv_bfloat16* __restrict__ Asrc;
        size_t abase;
        if (sub == 0) {   // x part (h-independent)
            Asrc  = hi ? g_xh : g_xl;
            abase = (size_t)(row0 + r) * XCOLS + (size_t)t * INSZ;
        } else {
            Asrc  = hi ? g_hh[buf] : g_hl[buf];
            abase = (size_t)(row0 + r) * HID + (size_t)(sub - 1) * KTILE;
        }
        abase += (size_t)quart * 16;
        const uint32_t ao = (uint32_t)(jid % 3) * 16384;
#pragma unroll
        for (int c = 0; c < 2; ++c)
            cp16(sA0 + ao + SWZ(rowoff + c * 16), Asrc + abase + c * 8);
        if (hi) {
            const size_t bbase = (size_t)(col0 + r) * KTOT
                                 + (size_t)sub * KTILE + (size_t)quart * 16;
            const uint32_t bo = (uint32_t)(sub & 1) * 16384;
#pragma unroll
            for (int c = 0; c < 2; ++c)
                cp16(sBL0 + bo + SWZ(rowoff + c * 16), g_Bl + bbase + c * 8);
        }
        cp_commit();
    };

    // prologue: x jobs of step 0
    issue_job(0, 0, 0);
    issue_job(1, 0, 0);

    for (int t = 0; t < TSTEPS; ++t) {
        const int buf  = t & 1;
        const int nbuf = buf ^ 1;

        // wait for row-group barrier: h[t] fully written (arrival posted at
        // end of step t-1). Overlaps with in-flight x loads of this step.
        if (t > 0) {
            if (tid == 0) {
                const unsigned long long target =
                    (unsigned long long)t * (unsigned long long)NROWCTA;
                unsigned long long cur;
                unsigned long long* p = &g_row_ticket[blockIdx.y * 16];
                do {
                    asm volatile("ld.acquire.gpu.u64 %0, [%1];" : "=l"(cur) : "l"(p));
                } while (cur < target);
            }
            __syncthreads();
        }

        float acc[2][4][4];
#pragma unroll
        for (int mf = 0; mf < 2; ++mf)
#pragma unroll
            for (int nf = 0; nf < 4; ++nf)
#pragma unroll
                for (int u = 0; u < 4; ++u) acc[mf][nf][u] = 0.f;

        for (int j = 0; j < NJOBS; ++j) {
            if (j == NJOBS - 1) cp_wait<0>(); else cp_wait<1>();
            __syncthreads();

            if (j + 2 < NJOBS) {
                issue_job(j + 2, t, buf);
            } else if (j == NJOBS - 1 && t + 1 < TSTEPS) {
                // pre-issue h-independent x jobs of next step
                issue_job(0, t + 1, nbuf);
                issue_job(1, t + 1, nbuf);
            }

            const int sub = j >> 1;
            const bool hi = (j & 1) == 0;
            const uint32_t sA  = sA0 + (uint32_t)(j % 3) * 16384;
            const uint32_t sBH = sbase + SOFF_BH + (uint32_t)sub * 16384;
            const uint32_t sBL = sBL0 + (uint32_t)(sub & 1) * 16384;

#pragma unroll
            for (int kk = 0; kk < 4; ++kk) {
                uint32_t af[2][4];
#pragma unroll
                for (int mf = 0; mf < 2; ++mf)
                    ldsm4(af[mf], sA + SWZ((uint32_t)(arow + mf * 16) * 128
                                           + (uint32_t)(kk * 2 + ach) * 16));
                {
                    uint32_t bf[4][2];
#pragma unroll
                    for (int p = 0; p < 2; ++p) {
                        uint32_t rr[4];
                        ldsm4(rr, sBH + SWZ((uint32_t)(brow + p * 16) * 128
                                            + (uint32_t)(kk * 2 + bch) * 16));
                        bf[p * 2 + 0][0] = rr[0]; bf[p * 2 + 0][1] = rr[1];
                        bf[p * 2 + 1][0] = rr[2]; bf[p * 2 + 1][1] = rr[3];
                    }
#pragma unroll
                    for (int mf = 0; mf < 2; ++mf)
#pragma unroll
                        for (int nf = 0; nf < 4; ++nf)
                            mma16816(acc[mf][nf], af[mf], bf[nf]);
                }
                if (hi) {
                    uint32_t bf[4][2];
#pragma unroll
                    for (int p = 0; p < 2; ++p) {
                        uint32_t rr[4];
                        ldsm4(rr, sBL + SWZ((uint32_t)(brow + p * 16) * 128
                                            + (uint32_t)(kk * 2 + bch) * 16));
                        bf[p * 2 + 0][0] = rr[0]; bf[p * 2 + 0][1] = rr[1];
                        bf[p * 2 + 1][0] = rr[2]; bf[p * 2 + 1][1] = rr[3];
                    }
#pragma unroll
                    for (int mf = 0; mf < 2; ++mf)
#pragma unroll
                        for (int nf = 0; nf < 4; ++nf)
                            mma16816(acc[mf][nf], af[mf], bf[nf]);
                }
            }
        }

        // ---- fused LSTM epilogue ----
#pragma unroll
        for (int mf = 0; mf < 2; ++mf) {
#pragma unroll
            for (int nf = 0; nf < 4; ++nf) {
                const int cb = wn * 32 + nf * 8 + q * 2;
                const float b0 = sBias[cb], b1 = sBias[cb + 1];
#pragma unroll
                for (int rs = 0; rs < 2; ++rs) {
                    float v0 = acc[mf][nf][rs * 2 + 0] + b0;
                    float v1 = acc[mf][nf][rs * 2 + 1] + b1;
                    float x0 = ev ? fsig(v0) : ftanh(v0);
                    float x1 = fsig(v1);
                    float y0 = __shfl_xor_sync(0xffffffffu, x0, 1);
                    float y1 = __shfl_xor_sync(0xffffffffu, x1, 1);
                    if (ev) {
                        const int n = (col0 + cb) >> 2;
                        const int b = row0 + wm * 32 + (lane >> 2) + mf * 16 + rs * 8;
                        const size_t idx = (size_t)b * HID + n;
                        float cn = x1 * creg[mf][nf][rs] + x0 * y0;   // f*c + i*g
                        creg[mf][nf][rs] = cn;
                        float hn = y1 * ftanh(cn);                    // o * tanh(c)
                        __nv_bfloat16 hhi = __float2bfloat16(hn);
                        g_hh[nbuf][idx] = hhi;
                        g_hl[nbuf][idx] = __float2bfloat16(hn - __bfloat162float(hhi));
                    }
                }
            }
        }

        // post arrival for next step's row barrier
        if (t + 1 < TSTEPS) {
            __syncthreads();
            if (tid == 0) {
                __threadfence();
                atomicAdd(&g_row_ticket[blockIdx.y * 16], 1ULL);
            }
        }
    }
}

// ---------------- final linear ----------------
__global__ void final_linear_kernel(const float* __restrict__ W_lin,
                                    const float* __restrict__ b_lin,
                                    float* __restrict__ out, int buf)
{
    int b = blockIdx.x;
    int w = threadIdx.y;      // 0..9
    int lane = threadIdx.x;   // 0..31
    const __nv_bfloat16* hh = g_hh[buf] + (size_t)b * HID;
    const __nv_bfloat16* hl = g_hl[buf] + (size_t)b * HID;
    const float* wl = W_lin + (size_t)w * HID;
    float s = 0.f;
#pragma unroll 4
    for (int k = lane; k < HID; k += 32) {
        float h = __bfloat162float(hh[k]) + __bfloat162float(hl[k]);
        s += h * wl[k];
    }
#pragma unroll
    for (int off = 16; off; off >>= 1)
        s += __shfl_down_sync(0xffffffffu, s, off);
    if (lane == 0)
        out[b * 10 + w] = s + b_lin[w];
}

// ---------------- launch ----------------
extern "C" void kernel_launch(void* const* d_in, const int* in_sizes, int n_in,
                              void* d_out, int out_size)
{
    const float* x     = (const float*)d_in[0];
    const float* h0    = (const float*)d_in[1];
    const float* c0    = (const float*)d_in[2];
    const float* W_ih  = (const float*)d_in[3];
    const float* W_hh  = (const float*)d_in[4];
    const float* b_ih  = (const float*)d_in[5];
    const float* b_hh  = (const float*)d_in[6];
    const float* W_lin = (const float*)d_in[7];
    const float* b_lin = (const float*)d_in[8];
    float* out = (float*)d_out;

    cudaFuncSetAttribute(lstm_persistent,
                         cudaFuncAttributeMaxDynamicSharedMemorySize, SMEM_TOTAL);

    reset_tickets_kernel<<<1, 128>>>();
    prepack_x_kernel<<<2048, 256>>>(x);
    prepack_w_kernel<<<1024, 256>>>(W_ih, W_hh, b_ih, b_hh);
    init_state_kernel<<<512, 512>>>(h0);

    dim3 grid(GATES / BN, B_SZ / BM);   // 16 x 8 = 128 CTAs (all resident)
    lstm_persistent<<<grid, 512, SMEM_TOTAL>>>(c0);

    // 256 steps -> final h is in buffer 0
    final_linear_kernel<<<B_SZ, dim3(32, 10)>>>(W_lin, b_lin, out, 0);
}

// round 7
// speedup vs baseline: 3.0835x; 1.0266x over previous
#include <cuda_runtime.h>
#include <cuda_bf16.h>
#include <math.h>
#include <stdint.h>

// ---------------- problem constants ----------------
#define B_SZ   1024
#define HID    512
#define INSZ   64
#define TSTEPS 256
#define GATES  2048              // 4*HID
#define KTOT   576               // INSZ + HID
#define XCOLS  (TSTEPS * INSZ)   // 16384

// ---------------- GEMM tiling ----------------
#define BM 128
#define BN 128
#define KTILE 64                 // 64 bf16 = 128 bytes per row
#define NJOBS 18                 // interleaved: even=hi(sub), odd=lo(sub)
#define NROWCTA 16               // CTAs per row group (same blockIdx.y)

// SW128 swizzle (Swizzle<3,4,3>) on byte offsets within a tile
#define SWZ(o) ((o) ^ (((o) >> 3) & 0x70))

// dynamic smem layout (all tile bases 1024-aligned)
#define SOFF_BH    0                         // 9 x 16384 = 147456
#define SOFF_A     147456                    // 3 x 16384 (triple buffer)
#define SOFF_BL    (SOFF_A + 49152)          // 2 x 16384
#define SMEM_TOTAL (SOFF_BL + 32768)         // 229376

// ---------------- device scratch (no allocs allowed) ----------------
static __device__ __align__(256) __nv_bfloat16 g_xh[(size_t)B_SZ * XCOLS];
static __device__ __align__(256) __nv_bfloat16 g_xl[(size_t)B_SZ * XCOLS];
static __device__ __align__(256) __nv_bfloat16 g_Bh[GATES * KTOT];   // packed col = n*4+g
static __device__ __align__(256) __nv_bfloat16 g_Bl[GATES * KTOT];
static __device__ float        g_bias[GATES];
static __device__ __align__(256) __nv_bfloat16 g_hh[2][B_SZ * HID];
static __device__ __align__(256) __nv_bfloat16 g_hl[2][B_SZ * HID];
// per-row-group tickets, 128B apart; reset to 0 at the start of every launch
static __device__ unsigned long long g_row_ticket[8 * 16];

// ---------------- PTX helpers ----------------
__device__ __forceinline__ uint32_t smem_u32(const void* p) {
    uint32_t a;
    asm("{ .reg .u64 t; cvta.to.shared.u64 t, %1; cvt.u32.u64 %0, t; }"
        : "=r"(a) : "l"(p));
    return a;
}

__device__ __forceinline__ void cp16(uint32_t dst, const void* src) {
    asm volatile("cp.async.cg.shared.global [%0], [%1], 16;"
                 :: "r"(dst), "l"(src));
}
__device__ __forceinline__ void cp_commit() {
    asm volatile("cp.async.commit_group;" ::: "memory");
}
template<int N>
__device__ __forceinline__ void cp_wait() {
    asm volatile("cp.async.wait_group %0;" :: "n"(N) : "memory");
}

__device__ __forceinline__ void ldsm4(uint32_t* r, uint32_t addr) {
    asm volatile("ldmatrix.sync.aligned.m8n8.x4.shared.b16 {%0,%1,%2,%3}, [%4];"
                 : "=r"(r[0]), "=r"(r[1]), "=r"(r[2]), "=r"(r[3]) : "r"(addr));
}

__device__ __forceinline__ void mma16816(float* c, const uint32_t* a, const uint32_t* b) {
    asm volatile(
        "mma.sync.aligned.m16n8k16.row.col.f32.bf16.bf16.f32 "
        "{%0,%1,%2,%3}, {%4,%5,%6,%7}, {%8,%9}, {%0,%1,%2,%3};"
        : "+f"(c[0]), "+f"(c[1]), "+f"(c[2]), "+f"(c[3])
        : "r"(a[0]), "r"(a[1]), "r"(a[2]), "r"(a[3]), "r"(b[0]), "r"(b[1]));
}

__device__ __forceinline__ float fsig(float x) {
    float e = __expf(-x);
    return __fdividef(1.f, 1.f + e);
}
__device__ __forceinline__ float ftanh(float x) {
    return 2.f * fsig(2.f * x) - 1.f;
}

// ---------------- prepack kernels ----------------
__global__ void prepack_x_kernel(const float* __restrict__ x) {
    size_t idx = (size_t)blockIdx.x * blockDim.x + threadIdx.x;
    size_t stride = (size_t)gridDim.x * blockDim.x;
    const size_t total = (size_t)B_SZ * XCOLS;
    for (size_t i = idx; i < total; i += stride) {
        float v = x[i];
        __nv_bfloat16 hi = __float2bfloat16(v);
        g_xh[i] = hi;
        g_xl[i] = __float2bfloat16(v - __bfloat162float(hi));
    }
}

__global__ void prepack_w_kernel(const float* __restrict__ W_ih,
                                 const float* __restrict__ W_hh,
                                 const float* __restrict__ b_ih,
                                 const float* __restrict__ b_hh) {
    int idx = blockIdx.x * blockDim.x + threadIdx.x;
    int stride = gridDim.x * blockDim.x;
    const int total = GATES * KTOT;
    for (int i = idx; i < total; i += stride) {
        int col = i / KTOT;
        int k   = i - col * KTOT;
        int n = col >> 2, g = col & 3;
        int row = g * HID + n;
        float v = (k < INSZ) ? W_ih[row * INSZ + k] : W_hh[row * HID + (k - INSZ)];
        __nv_bfloat16 hi = __float2bfloat16(v);
        g_Bh[i] = hi;
        g_Bl[i] = __float2bfloat16(v - __bfloat162float(hi));
    }
    for (int i = idx; i < GATES; i += stride) {
        int n = i >> 2, g = i & 3;
        int row = g * HID + n;
        g_bias[i] = b_ih[row] + b_hh[row];
    }
}

__global__ void init_state_kernel(const float* __restrict__ h0) {
    int idx = blockIdx.x * blockDim.x + threadIdx.x;
    int stride = gridDim.x * blockDim.x;
    for (int i = idx; i < B_SZ * HID; i += stride) {
        float h = h0[i];
        __nv_bfloat16 hi = __float2bfloat16(h);
        g_hh[0][i] = hi;
        g_hl[0][i] = __float2bfloat16(h - __bfloat162float(hi));
    }
}

__global__ void reset_tickets_kernel() {
    if (threadIdx.x < 8 * 16) g_row_ticket[threadIdx.x] = 0ULL;
}

// ---------------- persistent LSTM kernel (512 threads) ----------------
__global__ __launch_bounds__(512, 1)
void lstm_persistent(const float* __restrict__ c0g)
{
    extern __shared__ char smem[];
    const uint32_t sbase = smem_u32(smem);
    const int tid  = threadIdx.x;
    const int wid  = tid >> 5;
    const int lane = tid & 31;
    const int row0 = blockIdx.y * BM;   // batch base
    const int col0 = blockIdx.x * BN;   // packed gate col base
    const int wm = wid & 3;             // 0..3 (M)
    const int wn = wid >> 2;            // 0..3 (N)

    // loader mapping: 512 threads cover 128 rows x 128B (32B per thread)
    const int r     = tid >> 2;
    const int quart = tid & 3;
    const uint32_t rowoff = (uint32_t)r * 128 + (uint32_t)quart * 32;

    // ---- load resident B_hi (9 chunks, 147KB) ----
    {
        const size_t bb = (size_t)(col0 + r) * KTOT + (size_t)quart * 16;
        for (int sub = 0; sub < 9; ++sub) {
            uint32_t dst = sbase + SOFF_BH + sub * 16384;
#pragma unroll
            for (int c = 0; c < 2; ++c)
                cp16(dst + SWZ(rowoff + c * 16), g_Bh + bb + sub * KTILE + c * 8);
        }
        cp_commit();
    }

    // ---- per-thread epilogue constants: c state + bias in registers ----
    const int q  = lane & 3;
    const bool ev = (q & 1) == 0;
    float creg[2][4][2];
    float bb0[4], bb1[4];
#pragma unroll
    for (int nf = 0; nf < 4; ++nf) {
        int cb = wn * 32 + nf * 8 + q * 2;
        bb0[nf] = g_bias[col0 + cb];
        bb1[nf] = g_bias[col0 + cb + 1];
#pragma unroll
        for (int mf = 0; mf < 2; ++mf)
#pragma unroll
            for (int rs = 0; rs < 2; ++rs) {
                int n = (col0 + cb) >> 2;
                int b = row0 + wm * 32 + (lane >> 2) + mf * 16 + rs * 8;
                creg[mf][nf][rs] = c0g[(size_t)b * HID + n];
            }
    }

    cp_wait<0>();
    __syncthreads();

    // fragment addressing constants
    const int lane7 = lane & 7;
    const int arow  = wm * 32 + ((lane >> 3) & 1) * 8 + lane7;   // + mf*16
    const int ach   = (lane >> 4) & 1;
    const int brow  = wn * 32 + ((lane >> 4) & 1) * 8 + lane7;   // + p*16
    const int bch   = (lane >> 3) & 1;

    const uint32_t sA0  = sbase + SOFF_A;
    const uint32_t sBL0 = sbase + SOFF_BL;

    // job jid: even = hi(sub=jid/2): A_hi x (B_hi + B_lo); odd = lo: A_lo x B_hi
    // A buffer = jid % 3 (triple); BL buffer = (jid/2) & 1 (double).
    auto issue_job = [&](int jid, int t, int buf) {
        const int sub = jid >> 1;
        const bool hi = (jid & 1) == 0;
        const __nv_bfloat16* __restrict__ Asrc;
        size_t abase;
        if (sub == 0) {   // x part (h-independent)
            Asrc  = hi ? g_xh : g_xl;
            abase = (size_t)(row0 + r) * XCOLS + (size_t)t * INSZ;
        } else {
            Asrc  = hi ? g_hh[buf] : g_hl[buf];
            abase = (size_t)(row0 + r) * HID + (size_t)(sub - 1) * KTILE;
        }
        abase += (size_t)quart * 16;
        const uint32_t ao = (uint32_t)(jid % 3) * 16384;
#pragma unroll
        for (int c = 0; c < 2; ++c)
            cp16(sA0 + ao + SWZ(rowoff + c * 16), Asrc + abase + c * 8);
        if (hi) {
            const size_t bbase = (size_t)(col0 + r) * KTOT
                                 + (size_t)sub * KTILE + (size_t)quart * 16;
            const uint32_t bo = (uint32_t)(sub & 1) * 16384;
#pragma unroll
            for (int c = 0; c < 2; ++c)
                cp16(sBL0 + bo + SWZ(rowoff + c * 16), g_Bl + bbase + c * 8);
        }
        cp_commit();
    };

    float acc[2][4][4];

    // MMA of one job on current acc
    auto mma_job = [&](int j) {
        const int sub = j >> 1;
        const bool hi = (j & 1) == 0;
        const uint32_t sA  = sA0 + (uint32_t)(j % 3) * 16384;
        const uint32_t sBH = sbase + SOFF_BH + (uint32_t)sub * 16384;
        const uint32_t sBL = sBL0 + (uint32_t)(sub & 1) * 16384;
#pragma unroll
        for (int kk = 0; kk < 4; ++kk) {
            uint32_t af[2][4];
#pragma unroll
            for (int mf = 0; mf < 2; ++mf)
                ldsm4(af[mf], sA + SWZ((uint32_t)(arow + mf * 16) * 128
                                       + (uint32_t)(kk * 2 + ach) * 16));
            {
                uint32_t bf[4][2];
#pragma unroll
                for (int p = 0; p < 2; ++p) {
                    uint32_t rr[4];
                    ldsm4(rr, sBH + SWZ((uint32_t)(brow + p * 16) * 128
                                        + (uint32_t)(kk * 2 + bch) * 16));
                    bf[p * 2 + 0][0] = rr[0]; bf[p * 2 + 0][1] = rr[1];
                    bf[p * 2 + 1][0] = rr[2]; bf[p * 2 + 1][1] = rr[3];
                }
#pragma unroll
                for (int mf = 0; mf < 2; ++mf)
#pragma unroll
                    for (int nf = 0; nf < 4; ++nf)
                        mma16816(acc[mf][nf], af[mf], bf[nf]);
            }
            if (hi) {
                uint32_t bf[4][2];
#pragma unroll
                for (int p = 0; p < 2; ++p) {
                    uint32_t rr[4];
                    ldsm4(rr, sBL + SWZ((uint32_t)(brow + p * 16) * 128
                                        + (uint32_t)(kk * 2 + bch) * 16));
                    bf[p * 2 + 0][0] = rr[0]; bf[p * 2 + 0][1] = rr[1];
                    bf[p * 2 + 1][0] = rr[2]; bf[p * 2 + 1][1] = rr[3];
                }
#pragma unroll
                for (int mf = 0; mf < 2; ++mf)
#pragma unroll
                    for (int nf = 0; nf < 4; ++nf)
                        mma16816(acc[mf][nf], af[mf], bf[nf]);
            }
        }
    };

    // prologue: x jobs of step 0
    issue_job(0, 0, 0);
    issue_job(1, 0, 0);

    for (int t = 0; t < TSTEPS; ++t) {
        const int buf  = t & 1;
        const int nbuf = buf ^ 1;

#pragma unroll
        for (int mf = 0; mf < 2; ++mf)
#pragma unroll
            for (int nf = 0; nf < 4; ++nf)
#pragma unroll
                for (int u = 0; u < 4; ++u) acc[mf][nf][u] = 0.f;

        // ---- job 0 (x hi): barrier-independent, hides the row-group spin ----
        cp_wait<1>();
        __syncthreads();
        mma_job(0);

        // ---- row-group barrier: h[t] visible (overlapped by job-0 MMA) ----
        if (t > 0 && tid == 0) {
            const unsigned long long target =
                (unsigned long long)t * (unsigned long long)NROWCTA;
            unsigned long long cur;
            unsigned long long* p = &g_row_ticket[blockIdx.y * 16];
            do {
                asm volatile("ld.acquire.gpu.u64 %0, [%1];" : "=l"(cur) : "l"(p));
            } while (cur < target);
        }
        __syncthreads();   // also orders job-0 MMA before buffer reuse below

        // now safe to touch h: issue first two h jobs
        issue_job(2, t, buf);
        issue_job(3, t, buf);

        // ---- job 1 (x lo) ----
        cp_wait<2>();
        __syncthreads();
        mma_job(1);

        // ---- jobs 2..17 steady state ----
        for (int j = 2; j < NJOBS; ++j) {
            if (j == NJOBS - 1) cp_wait<0>(); else cp_wait<1>();
            __syncthreads();
            if (j + 2 < NJOBS) {
                issue_job(j + 2, t, buf);
            } else if (j == NJOBS - 1 && t + 1 < TSTEPS) {
                // pre-issue h-independent x jobs of next step
                issue_job(0, t + 1, nbuf);
                issue_job(1, t + 1, nbuf);
            }
            mma_job(j);
        }

        // ---- fused LSTM epilogue ----
#pragma unroll
        for (int mf = 0; mf < 2; ++mf) {
#pragma unroll
            for (int nf = 0; nf < 4; ++nf) {
                const int cb = wn * 32 + nf * 8 + q * 2;
#pragma unroll
                for (int rs = 0; rs < 2; ++rs) {
                    float v0 = acc[mf][nf][rs * 2 + 0] + bb0[nf];
                    float v1 = acc[mf][nf][rs * 2 + 1] + bb1[nf];
                    float x0 = ev ? fsig(v0) : ftanh(v0);
                    float x1 = fsig(v1);
                    float y0 = __shfl_xor_sync(0xffffffffu, x0, 1);
                    float y1 = __shfl_xor_sync(0xffffffffu, x1, 1);
                    if (ev) {
                        const int n = (col0 + cb) >> 2;
                        const int b = row0 + wm * 32 + (lane >> 2) + mf * 16 + rs * 8;
                        const size_t idx = (size_t)b * HID + n;
                        float cn = x1 * creg[mf][nf][rs] + x0 * y0;   // f*c + i*g
                        creg[mf][nf][rs] = cn;
                        float hn = y1 * ftanh(cn);                    // o * tanh(c)
                        __nv_bfloat16 hhi = __float2bfloat16(hn);
                        g_hh[nbuf][idx] = hhi;
                        g_hl[nbuf][idx] = __float2bfloat16(hn - __bfloat162float(hhi));
                    }
                }
            }
        }

        // post arrival for next step's row barrier (release semantics)
        if (t + 1 < TSTEPS) {
            __syncthreads();
            if (tid == 0) {
                unsigned long long one = 1ULL;
                asm volatile("red.release.gpu.global.add.u64 [%0], %1;"
                             :: "l"(&g_row_ticket[blockIdx.y * 16]), "l"(one)
                             : "memory");
            }
        }
    }
}

// ---------------- final linear ----------------
__global__ void final_linear_kernel(const float* __restrict__ W_lin,
                                    const float* __restrict__ b_lin,
                                    float* __restrict__ out, int buf)
{
    int b = blockIdx.x;
    int w = threadIdx.y;      // 0..9
    int lane = threadIdx.x;   // 0..31
    const __nv_bfloat16* hh = g_hh[buf] + (size_t)b * HID;
    const __nv_bfloat16* hl = g_hl[buf] + (size_t)b * HID;
    const float* wl = W_lin + (size_t)w * HID;
    float s = 0.f;
#pragma unroll 4
    for (int k = lane; k < HID; k += 32) {
        float h = __bfloat162float(hh[k]) + __bfloat162float(hl[k]);
        s += h * wl[k];
    }
#pragma unroll
    for (int off = 16; off; off >>= 1)
        s += __shfl_down_sync(0xffffffffu, s, off);
    if (lane == 0)
        out[b * 10 + w] = s + b_lin[w];
}

// ---------------- launch ----------------
extern "C" void kernel_launch(void* const* d_in, const int* in_sizes, int n_in,
                              void* d_out, int out_size)
{
    const float* x     = (const float*)d_in[0];
    const float* h0    = (const float*)d_in[1];
    const float* c0    = (const float*)d_in[2];
    const float* W_ih  = (const float*)d_in[3];
    const float* W_hh  = (const float*)d_in[4];
    const float* b_ih  = (const float*)d_in[5];
    const float* b_hh  = (const float*)d_in[6];
    const float* W_lin = (const float*)d_in[7];
    const float* b_lin = (const float*)d_in[8];
    float* out = (float*)d_out;

    cudaFuncSetAttribute(lstm_persistent,
                         cudaFuncAttributeMaxDynamicSharedMemorySize, SMEM_TOTAL);

    reset_tickets_kernel<<<1, 128>>>();
    prepack_x_kernel<<<2048, 256>>>(x);
    prepack_w_kernel<<<1024, 256>>>(W_ih, W_hh, b_ih, b_hh);
    init_state_kernel<<<512, 512>>>(h0);

    dim3 grid(GATES / BN, B_SZ / BM);   // 16 x 8 = 128 CTAs (all resident)
    lstm_persistent<<<grid, 512, SMEM_TOTAL>>>(c0);

    // 256 steps -> final h is in buffer 0
    final_linear_kernel<<<B_SZ, dim3(32, 10)>>>(W_lin, b_lin, out, 0);
}